// round 7
// baseline (speedup 1.0000x reference)
#include <cuda_runtime.h>
#include <math.h>
#include <cstdint>

// Problem sizes
#define Bv 256
#define Tv 512
#define Fv 512
#define Hv 512
#define FH 2048
#define LBLK 64          // blocks per layer (8 units/block, 1 warp/unit)
#define GRIDP 128

// ---------------- device scratch (no allocations allowed) ----------------
__device__ __align__(16) float gZ1[Bv * FH];      // x[:,T-1,:] @ Wi1 + b1
__device__ __align__(16) float gH1all[Bv * Hv];   // h1 history
__device__ __align__(16) float gH2all[Bv * Hv];   // h2 history (= "last" matrix)
__device__ __align__(128) int g_cnt1[32];         // layer1 arrivals (64/step), padded line
__device__ __align__(128) int g_cnt2[32];         // layer2 arrivals (64/step), padded line

__device__ __forceinline__ int ld_acq(const int* p) {
    int v;
    asm volatile("ld.acquire.gpu.global.b32 %0, [%1];" : "=r"(v) : "l"(p));
    return v;
}
__device__ __forceinline__ float4 ldcg4(const float* p) {
    float4 v;
    asm volatile("ld.global.cg.v4.f32 {%0,%1,%2,%3}, [%4];"
                 : "=f"(v.x), "=f"(v.y), "=f"(v.z), "=f"(v.w) : "l"(p));
    return v;
}
__device__ __forceinline__ float ldcg(const float* p) {
    float v;
    asm volatile("ld.global.cg.f32 %0, [%1];" : "=f"(v) : "l"(p));
    return v;
}
__device__ __forceinline__ float sigf(float x)  { return 1.0f / (1.0f + __expf(-x)); }
__device__ __forceinline__ float tanhx(float x) { return 1.0f - 2.0f / (__expf(2.0f * x) + 1.0f); }

// ---------------- Phase A: Z1 = x[:,T-1,:] @ Wi1 + b1 (tiled, validated R3) ----------------
__global__ void gemmZ1(const float* __restrict__ x,
                       const float* __restrict__ Wi1,
                       const float* __restrict__ b1) {
    if (blockIdx.x == 0 && blockIdx.y == 0 && threadIdx.x == 0) { g_cnt1[0] = 0; g_cnt2[0] = 0; }

    __shared__ __align__(16) float sx[32][33];
    __shared__ __align__(16) float sw[32 * 128];

    const int tid = threadIdx.x;
    const int c0  = blockIdx.x * 128;
    const int b0  = blockIdx.y * 32;
    const int ct  = tid & 31;
    const int bt  = tid >> 5;

    float acc[4][4] = {};

    for (int f0 = 0; f0 < Fv; f0 += 32) {
        {
            int bb = tid >> 3;
            int ff = (tid & 7) * 4;
            const float* xp = x + (size_t)(b0 + bb) * Tv * Fv + (size_t)(Tv - 1) * Fv + f0 + ff;
            float4 v = *(const float4*)xp;
            sx[bb][ff + 0] = v.x; sx[bb][ff + 1] = v.y;
            sx[bb][ff + 2] = v.z; sx[bb][ff + 3] = v.w;
        }
        #pragma unroll
        for (int r = 0; r < 4; r++) {
            int linear = r * 256 + tid;
            int ff = linear >> 5;
            int cc = (linear & 31) * 4;
            float4 v = *(const float4*)(Wi1 + (size_t)(f0 + ff) * FH + c0 + cc);
            *(float4*)&sw[ff * 128 + cc] = v;
        }
        __syncthreads();
        #pragma unroll
        for (int ff = 0; ff < 32; ff++) {
            float4 wv = *(const float4*)&sw[ff * 128 + ct * 4];
            #pragma unroll
            for (int bi = 0; bi < 4; bi++) {
                float xv = sx[bt * 4 + bi][ff];
                acc[bi][0] = fmaf(xv, wv.x, acc[bi][0]);
                acc[bi][1] = fmaf(xv, wv.y, acc[bi][1]);
                acc[bi][2] = fmaf(xv, wv.z, acc[bi][2]);
                acc[bi][3] = fmaf(xv, wv.w, acc[bi][3]);
            }
        }
        __syncthreads();
    }
    const int c = c0 + ct * 4;
    float4 bv = *(const float4*)(b1 + c);
    #pragma unroll
    for (int bi = 0; bi < 4; bi++) {
        int b = b0 + bt * 4 + bi;
        float4 o;
        o.x = acc[bi][0] + bv.x; o.y = acc[bi][1] + bv.y;
        o.z = acc[bi][2] + bv.z; o.w = acc[bi][3] + bv.w;
        *(float4*)&gZ1[(size_t)b * FH + c] = o;
    }
}

// ---------------- Phase B: persistent, warp-per-unit, smem-free step loop ----------------
// Blocks 0..63   : layer1. Warp w owns unit u = bx*8+w. Lane l: k in [16l,16l+16).
// Blocks 64..127 : layer2. Warp w owns unit u = (bx-64)*8+w. Lane l: k in [32l,32l+32)
//                  (k<512 -> Wi2/h1, k>=512 -> Wh2/h2prev).
// All 4 gate dots per warp; butterfly shuffle reduce; lane 0 computes gates,
// keeps cell state in a register, stores 1 float of h. One __syncthreads per
// step (pre-arrive). Per-warp counter poll on entry.
__global__ void __launch_bounds__(256, 1) lstmPersist(
    const float* __restrict__ Wh1, const float* __restrict__ Wi2,
    const float* __restrict__ Wh2, const float* __restrict__ b2,
    const float* __restrict__ Wd,  const float* __restrict__ bd,
    float* __restrict__ out)
{
    const int tid  = threadIdx.x;
    const int bx   = blockIdx.x;
    const int w    = tid >> 5;
    const int lane = tid & 31;

    if (bx < LBLK) {
        // ================= layer 1 =================
        const int u = bx * 8 + w;
        // weights: rw[j][g] for k = lane*16+j, col = g*512+u
        float4 rw[16];   // .x=.gate0 .y=gate1 .z=gate2 .w=gate3 per k
        #pragma unroll
        for (int j = 0; j < 16; j++) {
            const float* Wp = Wh1 + (size_t)(lane * 16 + j) * FH + u;
            rw[j].x = __ldg(Wp);
            rw[j].y = __ldg(Wp + Hv);
            rw[j].z = __ldg(Wp + 2 * Hv);
            rw[j].w = __ldg(Wp + 3 * Hv);
        }
        float cst = 0.f;

        for (int s = 0; s < Bv; s++) {
            // prefetch z-input (lane 0 only; independent of poll)
            float4 zin = make_float4(0.f, 0.f, 0.f, 0.f);
            if (lane == 0) {
                const float* zp = gZ1 + (size_t)s * FH + u;
                zin.x = __ldg(zp); zin.y = __ldg(zp + Hv);
                zin.z = __ldg(zp + 2 * Hv); zin.w = __ldg(zp + 3 * Hv);
            }

            float hv[16];
            if (s > 0) {
                if (lane == 0) {
                    const int target = LBLK * s;
                    while (ld_acq(&g_cnt1[0]) < target) { }
                }
                __syncwarp();
                const float* hp = gH1all + (size_t)(s - 1) * Hv + lane * 16;
                #pragma unroll
                for (int q = 0; q < 4; q++) {
                    float4 t = ldcg4(hp + q * 4);
                    hv[q * 4 + 0] = t.x; hv[q * 4 + 1] = t.y;
                    hv[q * 4 + 2] = t.z; hv[q * 4 + 3] = t.w;
                }
            } else {
                #pragma unroll
                for (int j = 0; j < 16; j++) hv[j] = 0.f;
            }

            float a0 = 0.f, a1 = 0.f, a2 = 0.f, a3 = 0.f;
            #pragma unroll
            for (int j = 0; j < 16; j++) {
                a0 = fmaf(hv[j], rw[j].x, a0);
                a1 = fmaf(hv[j], rw[j].y, a1);
                a2 = fmaf(hv[j], rw[j].z, a2);
                a3 = fmaf(hv[j], rw[j].w, a3);
            }
            #pragma unroll
            for (int off = 16; off; off >>= 1) {
                a0 += __shfl_xor_sync(0xffffffffu, a0, off);
                a1 += __shfl_xor_sync(0xffffffffu, a1, off);
                a2 += __shfl_xor_sync(0xffffffffu, a2, off);
                a3 += __shfl_xor_sync(0xffffffffu, a3, off);
            }

            if (lane == 0) {
                float zi = a0 + zin.x, zf = a1 + zin.y, zg = a2 + zin.z, zo = a3 + zin.w;
                cst = sigf(zf) * cst + sigf(zi) * tanhx(zg);
                gH1all[(size_t)s * Hv + u] = sigf(zo) * tanhx(cst);
                __threadfence();
            }
            __syncthreads();
            if (tid == 0) atomicAdd(&g_cnt1[0], 1);
        }
    } else {
        // ================= layer 2 =================
        const int u = (bx - LBLK) * 8 + w;
        float4 rw[32];
        #pragma unroll
        for (int j = 0; j < 32; j++) {
            int k = lane * 32 + j;
            const float* Wp = (k < Hv ? Wi2 + (size_t)k * FH
                                      : Wh2 + (size_t)(k - Hv) * FH) + u;
            rw[j].x = __ldg(Wp);
            rw[j].y = __ldg(Wp + Hv);
            rw[j].z = __ldg(Wp + 2 * Hv);
            rw[j].w = __ldg(Wp + 3 * Hv);
        }
        float4 b2r = make_float4(0.f, 0.f, 0.f, 0.f);
        if (lane == 0) {
            b2r.x = __ldg(b2 + u);          b2r.y = __ldg(b2 + Hv + u);
            b2r.z = __ldg(b2 + 2 * Hv + u); b2r.w = __ldg(b2 + 3 * Hv + u);
        }
        float cst = 0.f;

        for (int s = 1; s <= Bv; s++) {
            if (lane == 0) {
                const int target1 = LBLK * s;
                while (ld_acq(&g_cnt1[0]) < target1) { }
                if (s >= 2) {
                    const int target2 = LBLK * (s - 1);
                    while (ld_acq(&g_cnt2[0]) < target2) { }
                }
            }
            __syncwarp();

            float hv[32];
            if (lane < 16) {   // k = lane*32 .. +31 in [0,512): h1[s-1]
                const float* hp = gH1all + (size_t)(s - 1) * Hv + lane * 32;
                #pragma unroll
                for (int q = 0; q < 8; q++) {
                    float4 t = ldcg4(hp + q * 4);
                    hv[q * 4 + 0] = t.x; hv[q * 4 + 1] = t.y;
                    hv[q * 4 + 2] = t.z; hv[q * 4 + 3] = t.w;
                }
            } else if (s >= 2) {  // k-512: h2[s-2]
                const float* hp = gH2all + (size_t)(s - 2) * Hv + (lane - 16) * 32;
                #pragma unroll
                for (int q = 0; q < 8; q++) {
                    float4 t = ldcg4(hp + q * 4);
                    hv[q * 4 + 0] = t.x; hv[q * 4 + 1] = t.y;
                    hv[q * 4 + 2] = t.z; hv[q * 4 + 3] = t.w;
                }
            } else {
                #pragma unroll
                for (int j = 0; j < 32; j++) hv[j] = 0.f;
            }

            float a0 = 0.f, a1 = 0.f, a2 = 0.f, a3 = 0.f;
            #pragma unroll
            for (int j = 0; j < 32; j++) {
                a0 = fmaf(hv[j], rw[j].x, a0);
                a1 = fmaf(hv[j], rw[j].y, a1);
                a2 = fmaf(hv[j], rw[j].z, a2);
                a3 = fmaf(hv[j], rw[j].w, a3);
            }
            #pragma unroll
            for (int off = 16; off; off >>= 1) {
                a0 += __shfl_xor_sync(0xffffffffu, a0, off);
                a1 += __shfl_xor_sync(0xffffffffu, a1, off);
                a2 += __shfl_xor_sync(0xffffffffu, a2, off);
                a3 += __shfl_xor_sync(0xffffffffu, a3, off);
            }

            if (lane == 0) {
                float zi = a0 + b2r.x, zf = a1 + b2r.y, zg = a2 + b2r.z, zo = a3 + b2r.w;
                cst = sigf(zf) * cst + sigf(zi) * tanhx(zg);
                gH2all[(size_t)(s - 1) * Hv + u] = sigf(zo) * tanhx(cst);
                __threadfence();
            }
            __syncthreads();
            if (tid == 0) atomicAdd(&g_cnt2[0], 1);
        }
    }

    // ================= fused output GEMM: out = gH2all @ Wd + bd =================
    if (tid == 0) {
        const int target2 = LBLK * Bv;
        while (ld_acq(&g_cnt2[0]) < target2) { }
    }
    __syncthreads();
    for (int m = bx; m < Bv; m += GRIDP) {
        for (int o = w; o < 10; o += 8) {
            float acc = 0.f;
            #pragma unroll
            for (int j = 0; j < 16; j++) {
                int k = lane * 16 + j;
                acc = fmaf(ldcg(&gH2all[(size_t)m * Hv + k]), __ldg(Wd + (size_t)k * 10 + o), acc);
            }
            #pragma unroll
            for (int off = 16; off; off >>= 1)
                acc += __shfl_xor_sync(0xffffffffu, acc, off);
            if (lane == 0) out[m * 10 + o] = acc + __ldg(bd + o);
        }
    }
}

// ---------------- launch ----------------
extern "C" void kernel_launch(void* const* d_in, const int* in_sizes, int n_in,
                              void* d_out, int out_size) {
    (void)in_sizes; (void)n_in; (void)out_size;
    const float* x   = (const float*)d_in[0];
    const float* Wi1 = (const float*)d_in[1];
    const float* Wh1 = (const float*)d_in[2];
    const float* b1  = (const float*)d_in[3];
    const float* Wi2 = (const float*)d_in[4];
    const float* Wh2 = (const float*)d_in[5];
    const float* b2  = (const float*)d_in[6];
    const float* Wd  = (const float*)d_in[7];
    const float* bd  = (const float*)d_in[8];
    float* out = (float*)d_out;

    gemmZ1<<<dim3(16, 8), 256>>>(x, Wi1, b1);
    lstmPersist<<<GRIDP, 256>>>(Wh1, Wi2, Wh2, b2, Wd, bd, out);
}

// round 10
// speedup vs baseline: 3.5291x; 3.5291x over previous
#include <cuda_runtime.h>
#include <math.h>
#include <cstdint>

// Problem sizes
#define Bv 256
#define Tv 512
#define Fv 512
#define Hv 512
#define FH 2048
#define LBLK 64          // blocks per layer (8 units/block, 1 warp/unit)
#define GRIDP 128

// ---------------- device scratch (no allocations allowed) ----------------
__device__ __align__(16) float gZ1[Bv * FH];      // x[:,T-1,:] @ Wi1 + b1
__device__ __align__(16) float gH1all[Bv * Hv];   // h1 history
__device__ __align__(16) float gH2all[Bv * Hv];   // h2 history (= "last" matrix)
__device__ __align__(128) int g_cnt1[32];         // layer1 arrivals (64/step), own line
__device__ __align__(128) int g_cnt2[32];         // layer2 arrivals (64/step), own line

// ---------------- helpers ----------------
__device__ __forceinline__ int ld_acq(const int* p) {
    int v;
    asm volatile("ld.acquire.gpu.global.b32 %0, [%1];" : "=r"(v) : "l"(p));
    return v;
}
__device__ __forceinline__ float ldcg(const float* p) {
    float v;
    asm volatile("ld.global.cg.f32 %0, [%1];" : "=f"(v) : "l"(p));
    return v;
}
__device__ __forceinline__ float sigf(float x)  { return 1.0f / (1.0f + __expf(-x)); }
__device__ __forceinline__ float tanhx(float x) { return 1.0f - 2.0f / (__expf(2.0f * x) + 1.0f); }

// ---------------- Phase A: Z1 = x[:,T-1,:] @ Wi1 + b1 (+ counter reset) ----------------
__global__ void gemmZ1(const float* __restrict__ x,
                       const float* __restrict__ Wi1,
                       const float* __restrict__ b1) {
    if (blockIdx.x == 0 && blockIdx.y == 0 && threadIdx.x == 0) {
        g_cnt1[0] = 0; g_cnt2[0] = 0;
    }

    __shared__ __align__(16) float sx[32][33];
    __shared__ __align__(16) float sw[32 * 128];

    const int tid = threadIdx.x;
    const int c0  = blockIdx.x * 128;
    const int b0  = blockIdx.y * 32;
    const int ct  = tid & 31;
    const int bt  = tid >> 5;

    float acc[4][4] = {};

    for (int f0 = 0; f0 < Fv; f0 += 32) {
        {
            int bb = tid >> 3;
            int ff = (tid & 7) * 4;
            const float* xp = x + (size_t)(b0 + bb) * Tv * Fv + (size_t)(Tv - 1) * Fv + f0 + ff;
            float4 v = *(const float4*)xp;
            sx[bb][ff + 0] = v.x; sx[bb][ff + 1] = v.y;
            sx[bb][ff + 2] = v.z; sx[bb][ff + 3] = v.w;
        }
        #pragma unroll
        for (int r = 0; r < 4; r++) {
            int linear = r * 256 + tid;
            int ff = linear >> 5;
            int cc = (linear & 31) * 4;
            float4 v = *(const float4*)(Wi1 + (size_t)(f0 + ff) * FH + c0 + cc);
            *(float4*)&sw[ff * 128 + cc] = v;
        }
        __syncthreads();
        #pragma unroll
        for (int ff = 0; ff < 32; ff++) {
            float4 wv = *(const float4*)&sw[ff * 128 + ct * 4];
            #pragma unroll
            for (int bi = 0; bi < 4; bi++) {
                float xv = sx[bt * 4 + bi][ff];
                acc[bi][0] = fmaf(xv, wv.x, acc[bi][0]);
                acc[bi][1] = fmaf(xv, wv.y, acc[bi][1]);
                acc[bi][2] = fmaf(xv, wv.z, acc[bi][2]);
                acc[bi][3] = fmaf(xv, wv.w, acc[bi][3]);
            }
        }
        __syncthreads();
    }
    const int c = c0 + ct * 4;
    float4 bv = *(const float4*)(b1 + c);
    #pragma unroll
    for (int bi = 0; bi < 4; bi++) {
        int b = b0 + bt * 4 + bi;
        float4 o;
        o.x = acc[bi][0] + bv.x; o.y = acc[bi][1] + bv.y;
        o.z = acc[bi][2] + bv.z; o.w = acc[bi][3] + bv.w;
        *(float4*)&gZ1[(size_t)b * FH + c] = o;
    }
}

// ---------------- Phase B: persistent; proven counter protocol + warp-per-unit compute ----------------
// Blocks 0..63   : layer1. Warp w owns unit u = bx*8+w; lane l holds Wh1 slice k in [16l,16l+16).
// Blocks 64..127 : layer2. Warp w owns unit u = (bx-64)*8+w; lane l holds slice k in [32l,32l+32)
//                  (k<512 -> Wi2 vs h1[s-1]; k>=512 -> Wh2 vs h2[s-2]).
// Per step: all threads ld.acquire-spin on the step counter(s), cooperatively stage h into
// smem (.cg), ONE sync, warp dot from smem + butterfly reduce, lane0 gates + 1 h store +
// threadfence, second sync, tid0 atomicAdd arrive. (Exact release/acquire chain of R4/R5/R6.)
__global__ void __launch_bounds__(256, 1) lstmPersist(
    const float* __restrict__ Wh1, const float* __restrict__ Wi2,
    const float* __restrict__ Wh2, const float* __restrict__ b2,
    const float* __restrict__ Wd,  const float* __restrict__ bd,
    float* __restrict__ out)
{
    __shared__ __align__(16) float sH[2][1024];

    const int tid  = threadIdx.x;
    const int bx   = blockIdx.x;
    const int w    = tid >> 5;
    const int lane = tid & 31;

    if (bx < LBLK) {
        // ================= layer 1 =================
        const int u = bx * 8 + w;
        float4 rw[16];   // rw[j] = Wh1[k=lane*16+j][gate 0..3 col u]
        #pragma unroll
        for (int j = 0; j < 16; j++) {
            const float* Wp = Wh1 + (size_t)(lane * 16 + j) * FH + u;
            rw[j].x = __ldg(Wp);
            rw[j].y = __ldg(Wp + Hv);
            rw[j].z = __ldg(Wp + 2 * Hv);
            rw[j].w = __ldg(Wp + 3 * Hv);
        }
        float cst = 0.f;

        for (int s = 0; s < Bv; s++) {
            const int sb = s & 1;

            // prefetch z-input (lane 0; gZ1 is pre-kernel data, no ordering needed)
            float4 zin = make_float4(0.f, 0.f, 0.f, 0.f);
            if (lane == 0) {
                const float* zp = gZ1 + (size_t)s * FH + u;
                zin.x = __ldg(zp); zin.y = __ldg(zp + Hv);
                zin.z = __ldg(zp + 2 * Hv); zin.w = __ldg(zp + 3 * Hv);
            }

            if (s > 0) {
                const int target = LBLK * s;
                while (ld_acq(&g_cnt1[0]) < target) { }
                const float* hp = gH1all + (size_t)(s - 1) * Hv;
                sH[sb][tid]       = ldcg(hp + tid);
                sH[sb][256 + tid] = ldcg(hp + 256 + tid);
            } else {
                sH[sb][tid] = 0.f; sH[sb][256 + tid] = 0.f;
            }
            __syncthreads();

            float a0 = 0.f, a1 = 0.f, a2 = 0.f, a3 = 0.f;
            const float* hp = &sH[sb][lane * 16];
            #pragma unroll
            for (int q = 0; q < 4; q++) {
                float4 t = *(const float4*)(hp + 4 * q);
                a0 = fmaf(t.x, rw[4*q+0].x, a0); a1 = fmaf(t.x, rw[4*q+0].y, a1);
                a2 = fmaf(t.x, rw[4*q+0].z, a2); a3 = fmaf(t.x, rw[4*q+0].w, a3);
                a0 = fmaf(t.y, rw[4*q+1].x, a0); a1 = fmaf(t.y, rw[4*q+1].y, a1);
                a2 = fmaf(t.y, rw[4*q+1].z, a2); a3 = fmaf(t.y, rw[4*q+1].w, a3);
                a0 = fmaf(t.z, rw[4*q+2].x, a0); a1 = fmaf(t.z, rw[4*q+2].y, a1);
                a2 = fmaf(t.z, rw[4*q+2].z, a2); a3 = fmaf(t.z, rw[4*q+2].w, a3);
                a0 = fmaf(t.w, rw[4*q+3].x, a0); a1 = fmaf(t.w, rw[4*q+3].y, a1);
                a2 = fmaf(t.w, rw[4*q+3].z, a2); a3 = fmaf(t.w, rw[4*q+3].w, a3);
            }
            #pragma unroll
            for (int off = 16; off; off >>= 1) {
                a0 += __shfl_xor_sync(0xffffffffu, a0, off);
                a1 += __shfl_xor_sync(0xffffffffu, a1, off);
                a2 += __shfl_xor_sync(0xffffffffu, a2, off);
                a3 += __shfl_xor_sync(0xffffffffu, a3, off);
            }
            if (lane == 0) {
                float zi = a0 + zin.x, zf = a1 + zin.y, zg = a2 + zin.z, zo = a3 + zin.w;
                cst = sigf(zf) * cst + sigf(zi) * tanhx(zg);
                gH1all[(size_t)s * Hv + u] = sigf(zo) * tanhx(cst);
                __threadfence();   // release h-store before block arrive
            }
            __syncthreads();
            if (tid == 0) atomicAdd(&g_cnt1[0], 1);
        }
    } else {
        // ================= layer 2 =================
        const int u = (bx - LBLK) * 8 + w;
        float4 rw[32];   // k = lane*32+j ; k<512: Wi2, else Wh2
        #pragma unroll
        for (int j = 0; j < 32; j++) {
            int k = lane * 32 + j;
            const float* Wp = (k < Hv ? Wi2 + (size_t)k * FH
                                      : Wh2 + (size_t)(k - Hv) * FH) + u;
            rw[j].x = __ldg(Wp);
            rw[j].y = __ldg(Wp + Hv);
            rw[j].z = __ldg(Wp + 2 * Hv);
            rw[j].w = __ldg(Wp + 3 * Hv);
        }
        float4 b2r = make_float4(0.f, 0.f, 0.f, 0.f);
        if (lane == 0) {
            b2r.x = __ldg(b2 + u);          b2r.y = __ldg(b2 + Hv + u);
            b2r.z = __ldg(b2 + 2 * Hv + u); b2r.w = __ldg(b2 + 3 * Hv + u);
        }
        float cst = 0.f;

        for (int s = 1; s <= Bv; s++) {
            const int sb = s & 1;

            {   // need h1[s-1]: layer1 step s-1 done
                const int t1 = LBLK * s;
                while (ld_acq(&g_cnt1[0]) < t1) { }
            }
            if (s >= 2) {   // need h2[s-2]: layer2 step s-1 done
                const int t2 = LBLK * (s - 1);
                while (ld_acq(&g_cnt2[0]) < t2) { }
            }

            {
                const float* hp1 = gH1all + (size_t)(s - 1) * Hv;
                sH[sb][tid]       = ldcg(hp1 + tid);
                sH[sb][256 + tid] = ldcg(hp1 + 256 + tid);
                if (s >= 2) {
                    const float* hp2 = gH2all + (size_t)(s - 2) * Hv;
                    sH[sb][512 + tid] = ldcg(hp2 + tid);
                    sH[sb][768 + tid] = ldcg(hp2 + 256 + tid);
                } else {
                    sH[sb][512 + tid] = 0.f;
                    sH[sb][768 + tid] = 0.f;
                }
            }
            __syncthreads();

            float a0 = 0.f, a1 = 0.f, a2 = 0.f, a3 = 0.f;
            const float* hp = &sH[sb][lane * 32];
            #pragma unroll
            for (int q = 0; q < 8; q++) {
                float4 t = *(const float4*)(hp + 4 * q);
                a0 = fmaf(t.x, rw[4*q+0].x, a0); a1 = fmaf(t.x, rw[4*q+0].y, a1);
                a2 = fmaf(t.x, rw[4*q+0].z, a2); a3 = fmaf(t.x, rw[4*q+0].w, a3);
                a0 = fmaf(t.y, rw[4*q+1].x, a0); a1 = fmaf(t.y, rw[4*q+1].y, a1);
                a2 = fmaf(t.y, rw[4*q+1].z, a2); a3 = fmaf(t.y, rw[4*q+1].w, a3);
                a0 = fmaf(t.z, rw[4*q+2].x, a0); a1 = fmaf(t.z, rw[4*q+2].y, a1);
                a2 = fmaf(t.z, rw[4*q+2].z, a2); a3 = fmaf(t.z, rw[4*q+2].w, a3);
                a0 = fmaf(t.w, rw[4*q+3].x, a0); a1 = fmaf(t.w, rw[4*q+3].y, a1);
                a2 = fmaf(t.w, rw[4*q+3].z, a2); a3 = fmaf(t.w, rw[4*q+3].w, a3);
            }
            #pragma unroll
            for (int off = 16; off; off >>= 1) {
                a0 += __shfl_xor_sync(0xffffffffu, a0, off);
                a1 += __shfl_xor_sync(0xffffffffu, a1, off);
                a2 += __shfl_xor_sync(0xffffffffu, a2, off);
                a3 += __shfl_xor_sync(0xffffffffu, a3, off);
            }
            if (lane == 0) {
                float zi = a0 + b2r.x, zf = a1 + b2r.y, zg = a2 + b2r.z, zo = a3 + b2r.w;
                cst = sigf(zf) * cst + sigf(zi) * tanhx(zg);
                gH2all[(size_t)(s - 1) * Hv + u] = sigf(zo) * tanhx(cst);
                __threadfence();   // release h-store before block arrive
            }
            __syncthreads();
            if (tid == 0) atomicAdd(&g_cnt2[0], 1);
        }
    }

    // ================= fused output GEMM: out = gH2all @ Wd + bd =================
    {   // proven gate: all layer2 steps arrived (acquire orders the row reads below)
        const int t2 = LBLK * Bv;
        while (ld_acq(&g_cnt2[0]) < t2) { }
    }
    __syncthreads();   // last step may still be reading sH buffers
    for (int m = bx; m < Bv; m += GRIDP) {
        {
            const float* hp = gH2all + (size_t)m * Hv;
            sH[0][tid]       = ldcg(hp + tid);
            sH[0][256 + tid] = ldcg(hp + 256 + tid);
        }
        __syncthreads();
        for (int o = w; o < 10; o += 8) {
            float acc = 0.f;
            #pragma unroll
            for (int j = 0; j < 16; j++) {
                int k = lane * 16 + j;
                acc = fmaf(sH[0][k], __ldg(Wd + (size_t)k * 10 + o), acc);
            }
            #pragma unroll
            for (int off = 16; off; off >>= 1)
                acc += __shfl_xor_sync(0xffffffffu, acc, off);
            if (lane == 0) out[m * 10 + o] = acc + __ldg(bd + o);
        }
        __syncthreads();
    }
}

// ---------------- launch ----------------
extern "C" void kernel_launch(void* const* d_in, const int* in_sizes, int n_in,
                              void* d_out, int out_size) {
    (void)in_sizes; (void)n_in; (void)out_size;
    const float* x   = (const float*)d_in[0];
    const float* Wi1 = (const float*)d_in[1];
    const float* Wh1 = (const float*)d_in[2];
    const float* b1  = (const float*)d_in[3];
    const float* Wi2 = (const float*)d_in[4];
    const float* Wh2 = (const float*)d_in[5];
    const float* b2  = (const float*)d_in[6];
    const float* Wd  = (const float*)d_in[7];
    const float* bd  = (const float*)d_in[8];
    float* out = (float*)d_out;

    gemmZ1<<<dim3(16, 8), 256>>>(x, Wi1, b1);
    lstmPersist<<<GRIDP, 256>>>(Wh1, Wi2, Wh2, b2, Wd, bd, out);
}